// round 16
// baseline (speedup 1.0000x reference)
#include <cuda_runtime.h>
#include <math.h>

#define D    16
#define KNN  16
#define FULL 0xffffffffu

#define NMAX 30720
#define MMAX 8192

#define G      24
#define NCELLS (G * G * G)        // 13824 fine cells (atoms)
#define HCELL  0.4f
#define GLO    (-4.8f)

#define GP     8                  // coarse grid for points (cell = 3 fine cells)
#define NPC    (GP * GP * GP)     // 512
#define CHY    24                 // chunk-groups of 4 warps -> cap 3072 pts/cell

// ---- scratch (static device globals; no allocation anywhere) ----
__device__ float4 g_atoms[MMAX];
__device__ float  g_u[MMAX * D];            // t @ W1[0:16,:]
__device__ int    g_cellid[MMAX];
__device__ __align__(16) int g_hist[NCELLS];
__device__ int    g_cellstart[NCELLS + 1];
__device__ int    g_cursor[NCELLS];
__device__ float4 g_satoms[MMAX];
__device__ int    g_sorig[MMAX];
// point sort (coarse grid)
__device__ int    g_pcell[NMAX];
__device__ __align__(16) int g_phist[NPC];
__device__ int    g_pstart[NPC + 1];
__device__ int    g_pcursor[NPC];
__device__ int    g_psort[NMAX];
// pipeline
__device__ int    g_idx[NMAX * KNN];
__device__ float  g_rinv[NMAX * KNN];
__device__ float  g_S1[NMAX * D];
__device__ float  g_S2[NMAX * D];
__device__ float  g_part1[2048 * 32];
__device__ float  g_part2[2048 * 32];
__device__ float  g_bn[64];
__device__ int    g_ctr1 = 0;
__device__ int    g_ctr2 = 0;

__device__ __forceinline__ unsigned fkey(float s) {
    unsigned b = __float_as_uint(s);
    return b ^ (((unsigned)((int)b >> 31)) | 0x80000000u);
}

// ---------------------------------------------------------------------------
__global__ __launch_bounds__(256) void zero_kernel()
{
    int i = blockIdx.x * 256 + threadIdx.x;
    if (i < NCELLS) g_hist[i] = 0;
    else if (i < NCELLS + NPC) g_phist[i - NCELLS] = 0;
}

// ---------------------------------------------------------------------------
// prep: atom MLP -> t; u = t @ W1[0:16,:]; coords/norm; fine cell id + hist.
// ---------------------------------------------------------------------------
__global__ __launch_bounds__(256) void prep_kernel(
    const float* __restrict__ atom_xyz, const float* __restrict__ atom_types,
    const float* __restrict__ Wt1, const float* __restrict__ bt1,
    const float* __restrict__ Wt2, const float* __restrict__ bt2,
    const float* __restrict__ Wt3, const float* __restrict__ bt3,
    const float* __restrict__ W1, int M)
{
    __shared__ float sW[4 * D * D];
    __shared__ float sB[3 * D];
    int tid = threadIdx.x;
    for (int t = tid; t < D * D; t += 256) {
        sW[t] = Wt1[t]; sW[256 + t] = Wt2[t]; sW[512 + t] = Wt3[t];
        sW[768 + t] = W1[t];
    }
    if (tid < D) { sB[tid] = bt1[tid]; sB[16 + tid] = bt2[tid]; sB[32 + tid] = bt3[tid]; }
    __syncthreads();

    int lane = tid & 31, j = lane & 15, half = lane >> 4;
    int i = blockIdx.x * 16 + (tid >> 5) * 2 + half;
    bool valid = i < M;
    int ii = valid ? i : M - 1;

    float v = atom_types[ii * D + j];
#pragma unroll
    for (int l = 0; l < 3; l++) {
        float a = sB[l * 16 + j];
#pragma unroll
        for (int kk = 0; kk < D; kk++)
            a = fmaf(__shfl_sync(FULL, v, kk, 16), sW[l * 256 + kk * D + j], a);
        v = a > 0.f ? a : 0.2f * a;
    }
    float u = 0.f;
#pragma unroll
    for (int kk = 0; kk < D; kk++)
        u = fmaf(__shfl_sync(FULL, v, kk, 16), sW[768 + kk * D + j], u);

    if (valid) {
        g_u[i * D + j] = u;
        if (j == 0) {
            float x = atom_xyz[i * 3 + 0], y = atom_xyz[i * 3 + 1], z = atom_xyz[i * 3 + 2];
            g_atoms[i] = make_float4(x, y, z, x * x + y * y + z * z);
            int cx = min(max((int)floorf((x - GLO) / HCELL), 0), G - 1);
            int cy = min(max((int)floorf((y - GLO) / HCELL), 0), G - 1);
            int cz = min(max((int)floorf((z - GLO) / HCELL), 0), G - 1);
            int cell = (cz * G + cy) * G + cx;
            g_cellid[i] = cell;
            atomicAdd(&g_hist[cell], 1);
        }
    }
}

// ---------------------------------------------------------------------------
__global__ __launch_bounds__(256) void pcell_kernel(const float* __restrict__ xyz, int N)
{
    int i = blockIdx.x * 256 + threadIdx.x;
    if (i >= N) return;
    float x = xyz[i * 3 + 0], y = xyz[i * 3 + 1], z = xyz[i * 3 + 2];
    const float HC = 3.0f * HCELL;               // coarse cell width 1.2
    int cx = min(max((int)floorf((x - GLO) / HC), 0), GP - 1);
    int cy = min(max((int)floorf((y - GLO) / HC), 0), GP - 1);
    int cz = min(max((int)floorf((z - GLO) / HC), 0), GP - 1);
    int cell = (cz * GP + cy) * GP + cx;
    g_pcell[i] = cell;
    atomicAdd(&g_phist[cell], 1);
}

// ---------------------------------------------------------------------------
// scan: block 0 = atom hist (13824), block 1 = point hist (512).
// 16 cells/thread via int4 loads. Requires size % 16 == 0 (both are).
// ---------------------------------------------------------------------------
__global__ __launch_bounds__(1024) void scan_kernel()
{
    int which = blockIdx.x;
    const int size = which ? NPC : NCELLS;
    const int4* hist4 = which ? (const int4*)g_phist : (const int4*)g_hist;
    int* start  = which ? g_pstart  : g_cellstart;
    int* cursor = which ? g_pcursor : g_cursor;

    __shared__ int wsum[32];
    int tid = threadIdx.x, lane = tid & 31, wid = tid >> 5;
    int base = tid * 16;
    int h[16];
    if (base < size) {
        int4 a = hist4[tid * 4 + 0], b = hist4[tid * 4 + 1];
        int4 c = hist4[tid * 4 + 2], d = hist4[tid * 4 + 3];
        h[0]=a.x; h[1]=a.y; h[2]=a.z; h[3]=a.w;
        h[4]=b.x; h[5]=b.y; h[6]=b.z; h[7]=b.w;
        h[8]=c.x; h[9]=c.y; h[10]=c.z; h[11]=c.w;
        h[12]=d.x; h[13]=d.y; h[14]=d.z; h[15]=d.w;
    } else {
#pragma unroll
        for (int q = 0; q < 16; q++) h[q] = 0;
    }
    int loc[16];
    int s = 0;
#pragma unroll
    for (int q = 0; q < 16; q++) { loc[q] = s; s += h[q]; }
    int v = s;
#pragma unroll
    for (int o = 1; o < 32; o <<= 1) {
        int t = __shfl_up_sync(FULL, v, o);
        if (lane >= o) v += t;
    }
    if (lane == 31) wsum[wid] = v;
    __syncthreads();
    if (tid < 32) {
        int t = wsum[tid];
#pragma unroll
        for (int o = 1; o < 32; o <<= 1) {
            int x = __shfl_up_sync(FULL, t, o);
            if (tid >= o) t += x;
        }
        wsum[tid] = t;
    }
    __syncthreads();
    int excl = (v - s) + (wid > 0 ? wsum[wid - 1] : 0);
    if (base < size) {
#pragma unroll
        for (int q = 0; q < 16; q++) {
            start[base + q]  = excl + loc[q];
            cursor[base + q] = excl + loc[q];
        }
        if (base + 16 == size) start[size] = excl + s;
    }
}

// ---------------------------------------------------------------------------
__global__ __launch_bounds__(256) void scatter_kernel(int M, int N)
{
    int a = blockIdx.x * 256 + threadIdx.x;
    if (a < M) {
        int cell = g_cellid[a];
        int pos = atomicAdd(&g_cursor[cell], 1);
        g_satoms[pos] = g_atoms[a];
        g_sorig[pos]  = a;
    }
    int p = a - ((M + 255) & ~255);
    if (p >= 0 && p < N) {
        int cell = g_pcell[p];
        int pos = atomicAdd(&g_pcursor[cell], 1);
        g_psort[pos] = p;
    }
}

// ---------------------------------------------------------------------------
// knn v5: warp = 32 points of ONE coarse cell (chunk).  Grid (NPC, CHY),
// 4 warps/block, warp w handles chunk blockIdx.y*4+w.  Candidate stream =
// expanding fine-cell cube around the coarse cell (identical for all lanes
// -> broadcast loads, contiguous row segments). Per-lane register sorted
// top-16 keys; per-lane exact cube-boundary termination; pass 2 recovers
// indices (<tau always, ==tau up to budget).
// ---------------------------------------------------------------------------
__global__ __launch_bounds__(128) void knn_kernel(const float* __restrict__ xyz)
{
    int cell = blockIdx.x;
    int wid = threadIdx.x >> 5, lane = threadIdx.x & 31;
    int p0 = g_pstart[cell], p1 = g_pstart[cell + 1];
    int pb = p0 + (blockIdx.y * 4 + wid) * 32;
    if (pb >= p1) return;

    int pi = pb + lane;
    bool valid = pi < p1;
    int pt = g_psort[valid ? pi : pb];
    float px = xyz[pt * 3 + 0], py = xyz[pt * 3 + 1], pz = xyz[pt * 3 + 2];
    const float cxm = -2.f * px, cym = -2.f * py, czm = -2.f * pz;
    const float pn = px * px + py * py + pz * pz;

    int ccx = cell % GP, ccy = (cell / GP) % GP, ccz = cell / (GP * GP);
    const int xlo = 3 * ccx, xhi = 3 * ccx + 2;
    const int ylo = 3 * ccy, yhi = 3 * ccy + 2;
    const int zlo = 3 * ccz, zhi = 3 * ccz + 2;

    unsigned k[16];
#pragma unroll
    for (int j = 0; j < 16; j++) k[j] = 0xFFFFFFFFu;

    int rfinal = 0;
    for (int r = 0; r <= G; r++) {
        if (r > 0) {
            int q = r - 1;
            float bd = 3.0e38f;
            int f;
            f = xlo - q; if (f > 0)     bd = fminf(bd, px - (GLO + f * HCELL));
            f = xhi + q; if (f < G - 1) bd = fminf(bd, (GLO + (f + 1) * HCELL) - px);
            f = ylo - q; if (f > 0)     bd = fminf(bd, py - (GLO + f * HCELL));
            f = yhi + q; if (f < G - 1) bd = fminf(bd, (GLO + (f + 1) * HCELL) - py);
            f = zlo - q; if (f > 0)     bd = fminf(bd, pz - (GLO + f * HCELL));
            f = zhi + q; if (f < G - 1) bd = fminf(bd, (GLO + (f + 1) * HCELL) - pz);
            float lim = bd * bd - pn;
            bool done = !valid || (k[15] < fkey(lim));
            if (__all_sync(FULL, done)) break;
        }
        rfinal = r;
        int zl = zlo - r, zh = zhi + r;
        int yl = ylo - r, yh = yhi + r;
        int xl = xlo - r, xh = xhi + r;
        for (int z = max(zl, 0); z <= min(zh, G - 1); z++) {
            bool zed = (z == zl || z == zh || r == 0);
            for (int y = max(yl, 0); y <= min(yh, G - 1); y++) {
                bool yed = (y == yl || y == yh);
                int rowb = (z * G + y) * G;
                int s0, e0, s1 = 0, e1 = 0;
                if (zed || yed) {
                    int x0 = max(xl, 0), x1 = min(xh, G - 1);
                    s0 = g_cellstart[rowb + x0];
                    e0 = g_cellstart[rowb + x1 + 1];
                } else {
                    if (xl >= 0) { s0 = g_cellstart[rowb + xl]; e0 = g_cellstart[rowb + xl + 1]; }
                    else         { s0 = 0; e0 = 0; }
                    if (xh < G)  { s1 = g_cellstart[rowb + xh]; e1 = g_cellstart[rowb + xh + 1]; }
                }
#pragma unroll 1
                for (int seg = 0; seg < 2; seg++) {
                    int ss = seg ? s1 : s0, ee = seg ? e1 : e0;
                    for (int a0 = ss; a0 < ee; a0 += 4) {
                        int n = ee - a0;
                        float4 at0 = g_satoms[a0];
                        float4 at1 = (n > 1) ? g_satoms[a0 + 1] : at0;
                        float4 at2 = (n > 2) ? g_satoms[a0 + 2] : at0;
                        float4 at3 = (n > 3) ? g_satoms[a0 + 3] : at0;
                        unsigned vq[4]; bool iq[4];
#pragma unroll
                        for (int q = 0; q < 4; q++) {
                            float4 at = (q == 0) ? at0 : (q == 1) ? at1 : (q == 2) ? at2 : at3;
                            float s = fmaf(cxm, at.x, at.w);
                            s = fmaf(cym, at.y, s);
                            s = fmaf(czm, at.z, s);
                            vq[q] = (q < n) ? fkey(s) : 0xFFFFFFFFu;
                            iq[q] = valid && (vq[q] < k[15]);
                        }
                        if (__any_sync(FULL, iq[0] | iq[1] | iq[2] | iq[3])) {
#pragma unroll
                            for (int q = 0; q < 4; q++) {
                                if (__any_sync(FULL, iq[q])) {
                                    unsigned vv = iq[q] ? vq[q] : 0xFFFFFFFFu;
#pragma unroll
                                    for (int j = 15; j >= 1; j--) {
                                        unsigned t = vv < k[j - 1] ? k[j - 1] : vv;
                                        k[j] = vv < k[j] ? t : k[j];
                                    }
                                    k[0] = vv < k[0] ? vv : k[0];
                                }
                            }
                        }
                    }
                }
            }
        }
    }

    // ---- pass 2: recover indices over cube radius rfinal ----
    unsigned tau = k[15];
    int c_less = 0;
#pragma unroll
    for (int j = 0; j < 15; j++) c_less += (k[j] < tau) ? 1 : 0;
    int budget = 16 - c_less;
    int c_lt = 0, c_eq = 0;

    for (int r = 0; r <= rfinal; r++) {
        int zl = zlo - r, zh = zhi + r;
        int yl = ylo - r, yh = yhi + r;
        int xl = xlo - r, xh = xhi + r;
        for (int z = max(zl, 0); z <= min(zh, G - 1); z++) {
            bool zed = (z == zl || z == zh || r == 0);
            for (int y = max(yl, 0); y <= min(yh, G - 1); y++) {
                bool yed = (y == yl || y == yh);
                int rowb = (z * G + y) * G;
                int s0, e0, s1 = 0, e1 = 0;
                if (zed || yed) {
                    int x0 = max(xl, 0), x1 = min(xh, G - 1);
                    s0 = g_cellstart[rowb + x0];
                    e0 = g_cellstart[rowb + x1 + 1];
                } else {
                    if (xl >= 0) { s0 = g_cellstart[rowb + xl]; e0 = g_cellstart[rowb + xl + 1]; }
                    else         { s0 = 0; e0 = 0; }
                    if (xh < G)  { s1 = g_cellstart[rowb + xh]; e1 = g_cellstart[rowb + xh + 1]; }
                }
#pragma unroll 1
                for (int seg = 0; seg < 2; seg++) {
                    int ss = seg ? s1 : s0, ee = seg ? e1 : e0;
#pragma unroll 4
                    for (int a = ss; a < ee; a++) {
                        float4 at = g_satoms[a];
                        float s = fmaf(cxm, at.x, at.w);
                        s = fmaf(cym, at.y, s);
                        s = fmaf(czm, at.z, s);
                        unsigned v = fkey(s);
                        bool lt = valid && v < tau;
                        bool eq = valid && v == tau && c_eq < budget;
                        if (lt | eq) {
                            int slot = lt ? c_lt : (c_less + c_eq);
                            if (lt) c_lt++; else c_eq++;
                            int orig = g_sorig[a];
                            float dx = px - at.x, dyy = py - at.y, dzz = pz - at.z;
                            float dd = fmaf(dzz, dzz, fmaf(dyy, dyy, dx * dx));
                            g_idx[pt * KNN + slot]  = orig;
                            g_rinv[pt * KNN + slot] = 1.0f / dd;
                        }
                    }
                }
            }
        }
    }
}

// ---------------------------------------------------------------------------
// stats1: h1 = leaky(u[ai] + rv*W1r + b1); BN1 sum/sumsq; ticket finalize.
// ---------------------------------------------------------------------------
__global__ __launch_bounds__(256) void stats1_kernel(
    const float* __restrict__ W1, const float* __restrict__ b1,
    const float* __restrict__ g1, const float* __restrict__ be1,
    int N, float inv_n)
{
    __shared__ float red[8 * 32];
    __shared__ float tot[32];
    __shared__ int   ticket;
    int tid = threadIdx.x;
    int lane = tid & 31, j = lane & 15;
    float b1j = b1[j];
    float wrj = W1[D * D + j];

    float s = 0.f, q = 0.f;
    int NR = N * KNN;
    for (int row = blockIdx.x * 16 + (tid >> 4); row < NR; row += gridDim.x * 16) {
        int   ai = g_idx[row];
        float rv = g_rinv[row];
        float a = g_u[ai * D + j] + b1j;
        a = fmaf(rv, wrj, a);
        float h = a > 0.f ? a : 0.2f * a;
        s += h;
        q = fmaf(h, h, q);
    }
    s += __shfl_xor_sync(FULL, s, 16);
    q += __shfl_xor_sync(FULL, q, 16);
    if (lane < 16) { red[(tid >> 5) * 32 + j] = s; red[(tid >> 5) * 32 + 16 + j] = q; }
    __syncthreads();
    if (tid < 32) {
        float acc = 0.f;
#pragma unroll
        for (int ww = 0; ww < 8; ww++) acc += red[ww * 32 + tid];
        g_part1[blockIdx.x * 32 + tid] = acc;
    }
    __threadfence();
    __syncthreads();
    if (tid == 0) ticket = atomicAdd(&g_ctr1, 1);
    __syncthreads();
    if (ticket == gridDim.x - 1) {
        int c = tid & 31, sl = tid >> 5;
        float acc = 0.f;
        for (int b = sl; b < (int)gridDim.x; b += 8) acc += g_part1[b * 32 + c];
        __syncthreads();
        red[sl * 32 + c] = acc;
        __syncthreads();
        if (tid < 32) {
            float t2 = 0.f;
#pragma unroll
            for (int ww = 0; ww < 8; ww++) t2 += red[ww * 32 + tid];
            tot[tid] = t2;
        }
        __syncthreads();
        if (tid < 16) {
            float mean = tot[tid] * inv_n;
            float var  = tot[16 + tid] * inv_n - mean * mean;
            float sc   = g1[tid] * rsqrtf(var + 1e-5f);
            g_bn[tid]      = sc;
            g_bn[16 + tid] = be1[tid] - mean * sc;
        }
        if (tid == 0) g_ctr1 = 0;
    }
}

// ---------------------------------------------------------------------------
// stats2: per point, pipelined neighbor loads; BN2 stats; ticket finalize.
// ---------------------------------------------------------------------------
__global__ __launch_bounds__(256) void stats2_kernel(
    const float* __restrict__ W1, const float* __restrict__ b1,
    const float* __restrict__ W2, const float* __restrict__ b2,
    const float* __restrict__ g2, const float* __restrict__ be2,
    int N, float inv_n)
{
    __shared__ float sW2[D * D];
    __shared__ float red[8 * 32];
    __shared__ float tot[32];
    __shared__ int   ticket;
    int tid = threadIdx.x;
    for (int t = tid; t < D * D; t += 256) sW2[t] = W2[t];
    __syncthreads();

    int lane = tid & 31, j = lane & 15, half = lane >> 4;
    int i = blockIdx.x * 16 + (tid >> 5) * 2 + half;
    bool valid = i < N;
    int ii = valid ? i : N - 1;
    float b1j = b1[j], b2j = b2[j];
    float wrj = W1[D * D + j];
    float sc1 = g_bn[j], sh1 = g_bn[16 + j];

    float S1 = 0.f, S2 = 0.f, Q2 = 0.f;
    int base = ii * KNN;
    float rv = g_rinv[base];
    float uj = g_u[g_idx[base] * D + j];
#pragma unroll 1
    for (int k = 0; k < KNN; k++) {
        float rv_n = 0.f, uj_n = 0.f;
        if (k + 1 < KNN) {
            rv_n = g_rinv[base + k + 1];
            uj_n = g_u[g_idx[base + k + 1] * D + j];
        }
        float a = uj + b1j;
        a = fmaf(rv, wrj, a);
        float h = a > 0.f ? a : 0.2f * a;
        S1 += h;
        float y = fmaf(h, sc1, sh1);
        float c = b2j;
#pragma unroll
        for (int kk = 0; kk < D; kk++)
            c = fmaf(__shfl_sync(FULL, y, kk, 16), sW2[kk * D + j], c);
        float h2 = c > 0.f ? c : 0.2f * c;
        S2 += h2;
        Q2 = fmaf(h2, h2, Q2);
        rv = rv_n; uj = uj_n;
    }
    if (valid) {
        g_S1[i * D + j] = S1;
        g_S2[i * D + j] = S2;
    } else { S2 = 0.f; Q2 = 0.f; }

    float s = S2 + __shfl_xor_sync(FULL, S2, 16);
    float q = Q2 + __shfl_xor_sync(FULL, Q2, 16);
    if (lane < 16) { red[(tid >> 5) * 32 + j] = s; red[(tid >> 5) * 32 + 16 + j] = q; }
    __syncthreads();
    if (tid < 32) {
        float acc = 0.f;
#pragma unroll
        for (int ww = 0; ww < 8; ww++) acc += red[ww * 32 + tid];
        g_part2[blockIdx.x * 32 + tid] = acc;
    }
    __threadfence();
    __syncthreads();
    if (tid == 0) ticket = atomicAdd(&g_ctr2, 1);
    __syncthreads();
    if (ticket == gridDim.x - 1) {
        int c = tid & 31, sl = tid >> 5;
        float acc = 0.f;
        for (int b = sl; b < (int)gridDim.x; b += 8) acc += g_part2[b * 32 + c];
        __syncthreads();
        red[sl * 32 + c] = acc;
        __syncthreads();
        if (tid < 32) {
            float t2 = 0.f;
#pragma unroll
            for (int ww = 0; ww < 8; ww++) t2 += red[ww * 32 + tid];
            tot[tid] = t2;
        }
        __syncthreads();
        if (tid < 16) {
            float mean = tot[tid] * inv_n;
            float var  = tot[16 + tid] * inv_n - mean * mean;
            float sc   = g2[tid] * rsqrtf(var + 1e-5f);
            g_bn[32 + tid] = sc;
            g_bn[48 + tid] = be2[tid] - mean * sc;
        }
        if (tid == 0) g_ctr2 = 0;
    }
}

// ---------------------------------------------------------------------------
__global__ __launch_bounds__(256) void final_kernel(
    const float* __restrict__ W3, const float* __restrict__ b3,
    float* __restrict__ out, int N)
{
    __shared__ float sW[2 * D * D];
    int tid = threadIdx.x;
    for (int t = tid; t < 2 * D * D; t += 256) sW[t] = W3[t];
    __syncthreads();

    int lane = tid & 31, j = lane & 15, half = lane >> 4;
    int i = blockIdx.x * 16 + (tid >> 5) * 2 + half;
    bool valid = i < N;
    int ii = valid ? i : N - 1;

    float fx1 = fmaf(g_S1[ii * D + j], g_bn[j],      (float)KNN * g_bn[16 + j]);
    float fx2 = fmaf(g_S2[ii * D + j], g_bn[32 + j], (float)KNN * g_bn[48 + j]);
    float o = b3[j];
#pragma unroll
    for (int kk = 0; kk < D; kk++)
        o = fmaf(__shfl_sync(FULL, fx1, kk, 16), sW[kk * D + j], o);
#pragma unroll
    for (int kk = 0; kk < D; kk++)
        o = fmaf(__shfl_sync(FULL, fx2, kk, 16), sW[(D + kk) * D + j], o);
    if (valid) out[i * D + j] = o;
}

// ---------------------------------------------------------------------------
extern "C" void kernel_launch(void* const* d_in, const int* in_sizes, int n_in,
                              void* d_out, int out_size)
{
    const float* xyz        = (const float*)d_in[0];
    const float* atom_xyz   = (const float*)d_in[1];
    const float* atom_types = (const float*)d_in[2];
    const float* Wt1 = (const float*)d_in[3];
    const float* bt1 = (const float*)d_in[4];
    const float* Wt2 = (const float*)d_in[5];
    const float* bt2 = (const float*)d_in[6];
    const float* Wt3 = (const float*)d_in[7];
    const float* bt3 = (const float*)d_in[8];
    const float* W1  = (const float*)d_in[9];
    const float* b1  = (const float*)d_in[10];
    const float* W2  = (const float*)d_in[11];
    const float* b2  = (const float*)d_in[12];
    const float* W3  = (const float*)d_in[13];
    const float* b3  = (const float*)d_in[14];
    const float* g1  = (const float*)d_in[15];
    const float* be1 = (const float*)d_in[16];
    const float* g2  = (const float*)d_in[17];
    const float* be2 = (const float*)d_in[18];

    int N = in_sizes[0] / 3;
    int M = in_sizes[1] / 3;
    float inv_n = 1.0f / (float)(N * KNN);

    zero_kernel<<<(NCELLS + NPC + 255) / 256, 256>>>();
    prep_kernel<<<(M + 15) / 16, 256>>>(atom_xyz, atom_types,
                                        Wt1, bt1, Wt2, bt2, Wt3, bt3, W1, M);
    pcell_kernel<<<(N + 255) / 256, 256>>>(xyz, N);
    scan_kernel<<<2, 1024>>>();
    {
        int mpad = (M + 255) & ~255;
        scatter_kernel<<<(mpad + N + 255) / 256, 256>>>(M, N);
    }

    {
        dim3 gk(NPC, CHY);
        knn_kernel<<<gk, 128>>>(xyz);
    }

    stats1_kernel<<<2048, 256>>>(W1, b1, g1, be1, N, inv_n);
    stats2_kernel<<<(N + 15) / 16, 256>>>(W1, b1, W2, b2, g2, be2, N, inv_n);
    final_kernel<<<(N + 15) / 16, 256>>>(W3, b3, (float*)d_out, N);
}